// round 17
// baseline (speedup 1.0000x reference)
#include <cuda_runtime.h>
#include <cstdint>

// ---------------------------------------------------------------------------
// StoX_Conv2d: 4-bit-weight / 4-plane-binarized-activation conv + per-chunk
// BatchNorm + stochastic MTJ binarization (exact JAX threefry reproduction).
// R16: R15 pipelined fat launches + FIX: kPrep grid now covers ALL of d_Sacc
//      (replay determinism — the += accumulator must be zeroed every call).
// ---------------------------------------------------------------------------

#define BATCH 8
#define CIN   64
#define LDIM  1024          // 32*32
#define OUTC  128
#define ABITS 4
#define GCH   9             // NUM_CHUNKS
#define CKTOT 576           // CIN*9
#define NTOT  32            // ABITS*BATCH
#define PSTR  1160          // padded 34x34 plane stride
#define TROW  904           // threshold table row stride

// ---- static device scratch (allocation-free rule: __device__ globals) -----
__device__ __align__(16) signed char d_SP[NTOT * CIN * PSTR];        // padded sign planes
__device__ __align__(16) int         d_Wp[144 * OUTC];               // packed quantized weights *7
__device__ __align__(16) short       d_t7[GCH * NTOT * OUTC * LDIM]; // 7*lt exact int
__device__ int                       d_S1[GCH * OUTC];               // exact sum(m)
__device__ long long                 d_S2[GCH * OUTC];               // exact sum(m^2)
__device__ __align__(16) int         d_Ti[GCH * OUTC * TROW];        // binarize thresholds
__device__ __align__(16) unsigned    d_Sacc[BATCH * OUTC * LDIM];    // packed (s+1) per a

struct Keys { unsigned v[2 * GCH]; };

// ---------------- Threefry2x32 (matches jax/_src/prng.py bit-exactly) ------
__host__ __device__ __forceinline__ unsigned rotl32(unsigned x, int r) {
#if defined(__CUDA_ARCH__)
    return __funnelshift_l(x, x, r);
#else
    return (x << r) | (x >> (32 - r));
#endif
}

__host__ __device__ __forceinline__ void tf2x32(unsigned k0, unsigned k1,
                                                unsigned x0, unsigned x1,
                                                unsigned& o0, unsigned& o1) {
    unsigned k2 = k0 ^ k1 ^ 0x1BD11BDAu;
    x0 += k0; x1 += k1;
#define TF_R(r) { x0 += x1; x1 = rotl32(x1, r); x1 ^= x0; }
    TF_R(13) TF_R(15) TF_R(26) TF_R(6)
    x0 += k1; x1 += k2 + 1u;
    TF_R(17) TF_R(29) TF_R(16) TF_R(24)
    x0 += k2; x1 += k0 + 2u;
    TF_R(13) TF_R(15) TF_R(26) TF_R(6)
    x0 += k0; x1 += k1 + 3u;
    TF_R(17) TF_R(29) TF_R(16) TF_R(24)
    x0 += k1; x1 += k2 + 4u;
    TF_R(13) TF_R(15) TF_R(26) TF_R(6)
    x0 += k2; x1 += k0 + 5u;
#undef TF_R
    o0 = x0; o1 = x1;
}

// ---------------- XLA EmitTanh f32 rational (un-fused mul/add) -------------
__device__ __forceinline__ float tanh_xla(float xin) {
    float x = fminf(fmaxf(xin, -9.0f), 9.0f);
    float x2 = __fmul_rn(x, x);
    float p = -2.76076847742355e-16f;
    p = __fadd_rn(__fmul_rn(x2, p),  2.00018790482477e-13f);
    p = __fadd_rn(__fmul_rn(x2, p), -8.60467152213735e-11f);
    p = __fadd_rn(__fmul_rn(x2, p),  5.12229709037114e-08f);
    p = __fadd_rn(__fmul_rn(x2, p),  1.48572235717979e-05f);
    p = __fadd_rn(__fmul_rn(x2, p),  6.37261928875436e-04f);
    p = __fadd_rn(__fmul_rn(x2, p),  4.89352455891786e-03f);
    float num = __fmul_rn(x, p);
    float q = 1.19825839466702e-06f;
    q = __fadd_rn(__fmul_rn(x2, q), 1.18534705686654e-04f);
    q = __fadd_rn(__fmul_rn(x2, q), 2.26843463243900e-03f);
    q = __fadd_rn(__fmul_rn(x2, q), 4.89352518554385e-03f);
    float r = __fdiv_rn(num, q);
    return (fabsf(xin) < 0.0004f) ? xin : r;
}

// ---------------- kPrep: zero d_Sacc (FULL range) + sign planes ------------
// grid must cover max(BATCH*OUTC*LDIM, BATCH*CIN*1156) = 1,048,576 threads.
__global__ void kPrep(const float* __restrict__ inp) {
    int i = blockIdx.x * 256 + threadIdx.x;
    if (i < BATCH * OUTC * LDIM) d_Sacc[i] = 0u;    // zero EVERY element, EVERY call
    if (i >= BATCH * CIN * 1156) return;
    int bc = i / 1156, p = i - bc * 1156;
    int y = p / 34, x = p - y * 34;
    const int AS = 512 * PSTR;                      // a-plane stride
    int base = bc * PSTR + p;
    if (y == 0 || y == 33 || x == 0 || x == 33) {
        d_SP[base] = 1;
        d_SP[AS + base] = -1;
        d_SP[2 * AS + base] = -1;
        d_SP[3 * AS + base] = -1;
    } else {
        float v = inp[(bc << 10) + (y - 1) * 32 + (x - 1)];
        float r = fminf(fmaxf(v, -1.0f), 1.0f);
        float half = 0.5f;
#pragma unroll
        for (int a = 0; a < ABITS; ++a) {
            bool pos = (r >= 0.0f);
            d_SP[a * AS + base] = pos ? 1 : -1;
            r = __fsub_rn(r, pos ? half : -half);
            half = __fmul_rn(half, 0.5f);
        }
    }
}

// ---------------- kW: weight standardize + 4-bit quantize ------------------
__global__ void kW(const float* __restrict__ wgt) {
    int o = blockIdx.x;                 // 128
    int t = threadIdx.x;                // 64
    __shared__ double red[64], red2[64];
    __shared__ float s_mean, s_std;
    const float* wr = wgt + o * CKTOT;

    double s = 0.0;
    for (int i = t; i < CKTOT; i += 64) s += (double)wr[i];
    red[t] = s; __syncthreads();
    for (int st = 32; st; st >>= 1) { if (t < st) red[t] += red[t + st]; __syncthreads(); }
    if (!t) s_mean = (float)(red[0] / 576.0);
    __syncthreads();
    float mf = s_mean;

    double s1 = 0.0, s2 = 0.0;
    for (int i = t; i < CKTOT; i += 64) {
        float bw = __fsub_rn(wr[i], mf);
        s1 += (double)bw; s2 += (double)bw * (double)bw;
    }
    red[t] = s1; red2[t] = s2; __syncthreads();
    for (int st = 32; st; st >>= 1) {
        if (t < st) { red[t] += red[t + st]; red2[t] += red2[t + st]; }
        __syncthreads();
    }
    if (!t) {
        double mu = red[0] / 576.0;
        double var = (red2[0] - 576.0 * mu * mu) / 575.0;  // ddof=1
        s_std = (float)sqrt(var);
    }
    __syncthreads();
    float stdf = s_std;

    for (int i = t; i < CKTOT; i += 64) {
        float bw = __fsub_rn(wr[i], mf);
        float c = fminf(fmaxf(__fdiv_rn(bw, stdf), -1.0f), 1.0f);
        int m = (int)rintf(__fmul_rn(c, 7.0f));   // round-half-even, like jnp.round
        ((signed char*)d_Wp)[(((unsigned)i >> 2) * OUTC + o) * 4 + (i & 3)] = (signed char)m;
    }
}

// ======================= fat kernel: 4 roles per launch =====================
// blocks [0,1024)    : kE  chunk i-3   (i in [3,11])
// blocks [1024,1088) : kG  chunk i     (i in [0,8])    (lh, n) = (bid&1, bid>>1)
// blocks [1088,1216) : kSt chunk i-1   (i in [1,9])
// blocks [1216,1344) : kT  chunk i-2   (i in [2,10])
__global__ void __launch_bounds__(256) kFat(int phase,
                                            const float* __restrict__ gamma,
                                            const float* __restrict__ beta,
                                            Keys keys) {
    __shared__ __align__(16) unsigned char SMEM[18688];
    int bid = blockIdx.x;
    int tid = threadIdx.x;

    if (bid < 1024) {
        // -------------------- kE: binarize + accumulate --------------------
        if (phase < 3 || phase > 11) return;
        int c = phase - 3;
        int o = bid & 127, b = bid >> 7;
        int* tt = (int*)SMEM;                        // 897 ints
        for (int idx = tid; idx < 897; idx += 256)
            tt[idx] = d_Ti[(c * OUTC + o) * TROW + idx];
        __syncthreads();
        unsigned k0 = keys.v[2 * c], k1 = keys.v[2 * c + 1];
#pragma unroll 1
        for (int it = 0; it < 4; ++it) {
            int l = it * 256 + tid;
            unsigned delta = 0;
#pragma unroll
            for (int a = 0; a < ABITS; ++a) {
                int n = a * 8 + b;
                int m7 = d_t7[((c * NTOT + n) << 17) + (o << 10) + l];
                int Vt = tt[m7 + 448];
                unsigned j = ((unsigned)(n * OUTC + o) << 10) + (unsigned)l;
                unsigned r0, r1; tf2x32(k0, k1, 0u, j, r0, r1);
                int v = (int)((r0 ^ r1) >> 9);
                int s = (v < Vt) ? 1 : -1;
                s = (Vt < 0) ? 0 : s;                // normed==0 -> 0
                delta += (unsigned)(s + 1) << (8 * a);
            }
            d_Sacc[((b * OUTC + o) << 10) + l] += delta;   // unique index: exact
        }
        return;
    }

    if (bid < 1088) {
        // -------------------- kG: fused unfold + dp4a GEMM -----------------
        if (phase > 8) return;
        int g = phase;
        int sb = bid - 1024;
        int lh = sb & 1, n = sb >> 1;
        int (*ws)[16] = (int(*)[16])SMEM;                       // 8KB
        signed char* sgn = (signed char*)(SMEM + 8192);         // 10.4KB

        for (int i = tid; i < OUTC * 16; i += 256) {
            int o = i >> 4, q = i & 15;
            ws[o][q] = d_Wp[(16 * g + q) * OUTC + o];
        }
        int c_lo = (64 * g) / 9;
        int cn = min(9, CIN - c_lo);
        {
            const int* src = (const int*)(d_SP + (n * CIN + c_lo) * PSTR);
            int* dst = (int*)sgn;
            int words = cn * (PSTR / 4);
            for (int i = tid; i < words; i += 256) dst[i] = src[i];
        }
        __syncthreads();

        int l0 = lh * 512 + 2 * tid;
        int l1 = l0 + 1;
        int px0 = (l0 >> 5) * 34 + (l0 & 31);
        int px1 = (l1 >> 5) * 34 + (l1 & 31);

        int A0[16], A1[16];
#pragma unroll
        for (int q = 0; q < 16; ++q) { A0[q] = 0; A1[q] = 0; }
#pragma unroll
        for (int q = 0; q < 16; ++q) {
#pragma unroll
            for (int s = 0; s < 4; ++s) {
                int ck = 64 * g + q * 4 + s;
                int cq = ck / 9;
                int kp = ck - 9 * cq;
                int dy = kp / 3, dx = kp - dy * 3;
                int boff = (cq - c_lo) * PSTR + dy * 34 + dx;   // block-uniform
                unsigned b0 = (unsigned char)sgn[boff + px0];
                unsigned b1 = (unsigned char)sgn[boff + px1];
                A0[q] |= b0 << (8 * s);
                A1[q] |= b1 << (8 * s);
            }
        }

        short* tb = d_t7 + ((g * NTOT + n) << 17) + l0;
#pragma unroll 2
        for (int o = 0; o < OUTC; o += 2) {
            int4 wa0 = *(const int4*)&ws[o][0];
            int4 wa1 = *(const int4*)&ws[o][4];
            int4 wa2 = *(const int4*)&ws[o][8];
            int4 wa3 = *(const int4*)&ws[o][12];
            int4 wb0 = *(const int4*)&ws[o + 1][0];
            int4 wb1 = *(const int4*)&ws[o + 1][4];
            int4 wb2 = *(const int4*)&ws[o + 1][8];
            int4 wb3 = *(const int4*)&ws[o + 1][12];
            int cA0 = 0, cA1 = 0, cB0 = 0, cB1 = 0;
            int dA0 = 0, dA1 = 0, dB0 = 0, dB1 = 0;
            cA0 = __dp4a(A0[0], wa0.x, cA0);  cA1 = __dp4a(A1[0], wa0.x, cA1);
            cB0 = __dp4a(A0[0], wb0.x, cB0);  cB1 = __dp4a(A1[0], wb0.x, cB1);
            dA0 = __dp4a(A0[8], wa2.x, dA0);  dA1 = __dp4a(A1[8], wa2.x, dA1);
            dB0 = __dp4a(A0[8], wb2.x, dB0);  dB1 = __dp4a(A1[8], wb2.x, dB1);
            cA0 = __dp4a(A0[1], wa0.y, cA0);  cA1 = __dp4a(A1[1], wa0.y, cA1);
            cB0 = __dp4a(A0[1], wb0.y, cB0);  cB1 = __dp4a(A1[1], wb0.y, cB1);
            dA0 = __dp4a(A0[9], wa2.y, dA0);  dA1 = __dp4a(A1[9], wa2.y, dA1);
            dB0 = __dp4a(A0[9], wb2.y, dB0);  dB1 = __dp4a(A1[9], wb2.y, dB1);
            cA0 = __dp4a(A0[2], wa0.z, cA0);  cA1 = __dp4a(A1[2], wa0.z, cA1);
            cB0 = __dp4a(A0[2], wb0.z, cB0);  cB1 = __dp4a(A1[2], wb0.z, cB1);
            dA0 = __dp4a(A0[10], wa2.z, dA0); dA1 = __dp4a(A1[10], wa2.z, dA1);
            dB0 = __dp4a(A0[10], wb2.z, dB0); dB1 = __dp4a(A1[10], wb2.z, dB1);
            cA0 = __dp4a(A0[3], wa0.w, cA0);  cA1 = __dp4a(A1[3], wa0.w, cA1);
            cB0 = __dp4a(A0[3], wb0.w, cB0);  cB1 = __dp4a(A1[3], wb0.w, cB1);
            dA0 = __dp4a(A0[11], wa2.w, dA0); dA1 = __dp4a(A1[11], wa2.w, dA1);
            dB0 = __dp4a(A0[11], wb2.w, dB0); dB1 = __dp4a(A1[11], wb2.w, dB1);
            cA0 = __dp4a(A0[4], wa1.x, cA0);  cA1 = __dp4a(A1[4], wa1.x, cA1);
            cB0 = __dp4a(A0[4], wb1.x, cB0);  cB1 = __dp4a(A1[4], wb1.x, cB1);
            dA0 = __dp4a(A0[12], wa3.x, dA0); dA1 = __dp4a(A1[12], wa3.x, dA1);
            dB0 = __dp4a(A0[12], wb3.x, dB0); dB1 = __dp4a(A1[12], wb3.x, dB1);
            cA0 = __dp4a(A0[5], wa1.y, cA0);  cA1 = __dp4a(A1[5], wa1.y, cA1);
            cB0 = __dp4a(A0[5], wb1.y, cB0);  cB1 = __dp4a(A1[5], wb1.y, cB1);
            dA0 = __dp4a(A0[13], wa3.y, dA0); dA1 = __dp4a(A1[13], wa3.y, dA1);
            dB0 = __dp4a(A0[13], wb3.y, dB0); dB1 = __dp4a(A1[13], wb3.y, dB1);
            cA0 = __dp4a(A0[6], wa1.z, cA0);  cA1 = __dp4a(A1[6], wa1.z, cA1);
            cB0 = __dp4a(A0[6], wb1.z, cB0);  cB1 = __dp4a(A1[6], wb1.z, cB1);
            dA0 = __dp4a(A0[14], wa3.z, dA0); dA1 = __dp4a(A1[14], wa3.z, dA1);
            dB0 = __dp4a(A0[14], wb3.z, dB0); dB1 = __dp4a(A1[14], wb3.z, dB1);
            cA0 = __dp4a(A0[7], wa1.w, cA0);  cA1 = __dp4a(A1[7], wa1.w, cA1);
            cB0 = __dp4a(A0[7], wb1.w, cB0);  cB1 = __dp4a(A1[7], wb1.w, cB1);
            dA0 = __dp4a(A0[15], wa3.w, dA0); dA1 = __dp4a(A1[15], wa3.w, dA1);
            dB0 = __dp4a(A0[15], wb3.w, dB0); dB1 = __dp4a(A1[15], wb3.w, dB1);

            short2 ra, rb;
            ra.x = (short)(cA0 + dA0); ra.y = (short)(cA1 + dA1);
            rb.x = (short)(cB0 + dB0); rb.y = (short)(cB1 + dB1);
            *(short2*)(tb + (o << 10)) = ra;
            *(short2*)(tb + ((o + 1) << 10)) = rb;
        }
        return;
    }

    if (bid < 1216) {
        // -------------------- kStats: exact sums per (c,o) -----------------
        if (phase < 1 || phase > 9) return;
        int c = phase - 1;
        int o = bid - 1088;
        int s1 = 0, s2 = 0;   // per-thread: 128 vals, |m|<=448 -> s2 <= 25.7M
        const short* base = d_t7 + ((c * NTOT) << 17) + (o << 10);
#pragma unroll 4
        for (int n = 0; n < NTOT; ++n) {
            int2 v = ((const int2*)(base + (n << 17)))[tid];
            int mA = (short)(v.x & 0xFFFF);
            int mB = (v.x >> 16);
            int mC = (short)(v.y & 0xFFFF);
            int mD = (v.y >> 16);
            s1 += mA + mB + mC + mD;
            s2 += mA * mA + mB * mB + mC * mC + mD * mD;
        }
        // warp reduce: warp s2 <= 822M fits int
#pragma unroll
        for (int d = 16; d; d >>= 1) {
            s1 += __shfl_xor_sync(0xFFFFFFFFu, s1, d);
            s2 += __shfl_xor_sync(0xFFFFFFFFu, s2, d);
        }
        int* r1 = (int*)SMEM;
        long long* r2 = (long long*)(SMEM + 64);
        int w = tid >> 5;
        if ((tid & 31) == 0) { r1[w] = s1; r2[w] = (long long)s2; }
        __syncthreads();
        if (tid == 0) {
            int t1 = 0; long long t2 = 0;
            for (int k = 0; k < 8; ++k) { t1 += r1[k]; t2 += r2[k]; }
            d_S1[c * OUTC + o] = t1;
            d_S2[c * OUTC + o] = t2;
        }
        return;
    }

    {
        // -------------------- kT: thresholds per (c,o) ---------------------
        if (phase < 2 || phase > 10) return;
        int c = phase - 2;
        int o = bid - 1216;
        int go = c * OUTC + o;
        __shared__ float s_mn, s_sf;
        if (tid == 0) {
            double mu  = (double)d_S1[go] / (7.0 * 32768.0);
            double ex2 = (double)d_S2[go] / (49.0 * 32768.0);
            double var = ex2 - mu * mu;          // biased (BN train)
            s_mn = (float)mu;
            s_sf = __fsqrt_rn(__fadd_rn((float)var, 1e-5f));
        }
        __syncthreads();
        float mn = s_mn, sd = s_sf;
        float gam = gamma[o], bet = beta[o];
        for (int idx = tid; idx < 897; idx += 256) {
            float lt = __fdiv_rn(__int2float_rn(idx - 448), 7.0f);
            float normed = __fadd_rn(__fmul_rn(__fdiv_rn(__fsub_rn(lt, mn), sd), gam), bet);
            float t = tanh_xla(__fmul_rn(normed, 4.0f));
            int Vt;
            if (t == 0.0f) {
                Vt = -1;                                    // sentinel -> s = 0
            } else {
                double thr = ((double)t + 1.0) * 4194304.0; // exact
                Vt = (int)ceil(thr);                        // v < Vt <=> t > rnd(v)
            }
            d_Ti[go * TROW + idx] = Vt;
        }
    }
}

// ---------------- kOut: recombine packed sums (identical op order) ---------
__global__ void kOut(float* __restrict__ out) {
    int idx = blockIdx.x * 256 + threadIdx.x;     // (b,o,l) flat, same layout
    if (idx >= BATCH * OUTC * LDIM) return;
    unsigned S = d_Sacc[idx];
    const float wts[ABITS] = {0.5f, 0.25f, 0.125f, 0.0625f};
    float acc = 0.0f;
#pragma unroll
    for (int a = 0; a < ABITS; ++a) {
        int Sa = (int)((S >> (8 * a)) & 255u) - 9;
        acc = __fadd_rn(acc, __fmul_rn(__fdiv_rn((float)Sa, 9.0f), wts[a]));
    }
    out[idx] = acc;
}

// ---------------------------------------------------------------------------
extern "C" void kernel_launch(void* const* d_in, const int* in_sizes, int n_in,
                              void* d_out, int out_size) {
    const float* inp   = (const float*)d_in[0];   // [8,64,32,32]
    const float* wgt   = (const float*)d_in[1];   // [128,64,3,3]
    const float* gamma = (const float*)d_in[2];   // [128]
    const float* beta  = (const float*)d_in[3];   // [128]
    float* out = (float*)d_out;                   // [8,128,32,32]

    // host-side key derivation: keys = split(key(42), 9) in partitionable mode
    Keys ks;
    for (int g = 0; g < GCH; ++g) {
        unsigned o0, o1;
        tf2x32(0u, 42u, 0u, (unsigned)g, o0, o1);
        ks.v[2 * g] = o0; ks.v[2 * g + 1] = o1;
    }

    // grid covers max(d_Sacc zeroing = 1,048,576, sign planes = 591,872)
    kPrep<<<(BATCH * OUTC * LDIM + 255) / 256, 256>>>(inp);
    kW<<<OUTC, 64>>>(wgt);
    for (int i = 0; i < 12; ++i)
        kFat<<<1344, 256>>>(i, gamma, beta, ks);
    kOut<<<(BATCH * OUTC * LDIM + 255) / 256, 256>>>(out);
}